// round 13
// baseline (speedup 1.0000x reference)
#include <cuda_runtime.h>
#include <cuda_fp16.h>
#include <cstdint>

// ---------------- problem constants ----------------
#define BATCH   2048
#define NATOM   96
#define NIN     128
#define NHID    64
#define SHIFTC  0.6931471805599453f
#define GRIDC   296            // 2 CTAs/SM x 148 SMs, single resident wave

// fp32 staging tile: 96 rows x (512B data + 32B pad) = 544B stride.
// LDS.64 fragment gather is conflict-free per 16-lane phase
// (word-bank pair = 8*qr + 2*qc, all 16 distinct, full 32-bank coverage).
#define ROWB   544
#define TILEB  (NATOM * ROWB)          // 52224 B
#define NBUF   2
#define SMEMB  (NBUF * TILEB + 32)     // + reduction slots

// ---------------- precomputed W1 fp16 image (B-fragment layout) ----------------
// uint2 index = (nt*8 + kt)*32 + lane ; .x = b0 (k pair, khalf 0), .y = b1 (khalf 1)
__device__ __align__(16) uint2 g_wh[2048];   // 16 KB, L1/L2-resident

__global__ void prep_w_kernel(const float* __restrict__ W1) {
    int idx = blockIdx.x * blockDim.x + threadIdx.x;
    if (idx >= NIN * NHID) return;
    int k = idx >> 6;          // 0..127
    int n = idx & 63;          // 0..63
    __half h = __float2half_rn(W1[idx]);
    int nt = n >> 3, g = n & 7;
    int kt = k >> 4, kl = k & 15;
    int tg = (kl >> 1) & 3, br = kl >> 3, odd = kl & 1;
    uint32_t off = (uint32_t)((((nt * 8 + kt) * 32 + (g * 4 + tg)) * 8) + br * 4 + odd * 2);
    *reinterpret_cast<__half*>(reinterpret_cast<unsigned char*>(g_wh) + off) = h;
}

// ---------------- device helpers ----------------
__device__ __forceinline__ void mma_f16(float* c, const uint32_t* a, const uint32_t* b) {
    asm volatile(
        "mma.sync.aligned.m16n8k16.row.col.f32.f16.f16.f32 "
        "{%0,%1,%2,%3}, {%4,%5,%6,%7}, {%8,%9}, {%0,%1,%2,%3};"
        : "+f"(c[0]), "+f"(c[1]), "+f"(c[2]), "+f"(c[3])
        : "r"(a[0]), "r"(a[1]), "r"(a[2]), "r"(a[3]), "r"(b[0]), "r"(b[1]));
}

__device__ __forceinline__ float ssp(float z) {
    // shifted softplus, numerically stable
    return fmaxf(z, 0.f) + __logf(1.f + __expf(-fabsf(z))) - SHIFTC;
}

__device__ __forceinline__ uint32_t cvt2h(float x, float y) {
    __half2 h = __floats2half2_rn(x, y);
    return *reinterpret_cast<uint32_t*>(&h);
}

__device__ __forceinline__ float2 lds64(uint32_t addr) {
    float2 v;
    asm volatile("ld.shared.v2.f32 {%0,%1}, [%2];" : "=f"(v.x), "=f"(v.y) : "r"(addr));
    return v;
}

// issue one sample's 48KB rep tile as a cp.async commit group (32 x 16B per thread)
__device__ __forceinline__ void prefetch_tile(const float* __restrict__ xb,
                                              uint32_t dstbase, int tid) {
    const char* g = reinterpret_cast<const char*>(xb);
    #pragma unroll
    for (int i = 0; i < 32; i++) {
        int idx = i * 96 + tid;
        int r = idx >> 5, c = idx & 31;
        asm volatile("cp.async.cg.shared.global [%0], [%1], 16;"
                     :: "r"(dstbase + (uint32_t)(r * ROWB + c * 16)),
                        "l"(g + (r * 512 + c * 16)));
    }
    asm volatile("cp.async.commit_group;" ::: "memory");
}

// ---------------- main fused kernel ----------------
// R12 post-mortem: DRAM% is bytes/duration, not the constraint — the kernel is
// phase-serialization bound (fill convoys with compute).  This version makes each
// CTA quasi-persistent: grid=296 (2/SM, one wave), each CTA strides ~7 samples with
// a 2-deep cp.async pipeline: issue prefetch of sample i+1, wait_group 1 (sample i
// ready while i+1 streams), compute i.  DRAM stays fed during compute; 2 CTAs/SM
// interleave out of phase.
__global__ void __launch_bounds__(96, 2)
atomwise_kernel(const float* __restrict__ rep,
                const int*   __restrict__ atomic_numbers,
                const float* __restrict__ atom_mask,
                const float* __restrict__ b1,
                const float* __restrict__ W2,
                const float* __restrict__ b2,
                const float* __restrict__ atomref,
                const float* __restrict__ mean,
                const float* __restrict__ stddev,
                float*       __restrict__ out) {
    extern __shared__ __align__(16) unsigned char smem[];
    float* red = reinterpret_cast<float*>(smem + NBUF * TILEB);

    const int tid  = threadIdx.x;
    const int w    = tid >> 5;          // warp 0..2
    const int lane = tid & 31;

    const int qr = lane >> 2;           // 0..7 (row group)
    const int qc = lane & 3;            // 0..3 (col pair)
    const int r0 = w * 32 + qr;         // rows r0, r0+8, r0+16, r0+24

    const uint32_t sb = (uint32_t)__cvta_generic_to_shared(smem);

    // prologue: prefetch first sample
    prefetch_tile(rep + (size_t)blockIdx.x * (NATOM * NIN), sb, tid);

    int buf = 0;
    for (int s = blockIdx.x; s < BATCH; s += GRIDC) {
        const int snext = s + GRIDC;
        if (snext < BATCH)
            prefetch_tile(rep + (size_t)snext * (NATOM * NIN),
                          sb + (uint32_t)((buf ^ 1) * TILEB), tid);

        // wait for current sample (allow next to keep streaming)
        if (snext < BATCH) asm volatile("cp.async.wait_group 1;" ::: "memory");
        else               asm volatile("cp.async.wait_group 0;" ::: "memory");
        __syncthreads();

        const uint32_t tb  = sb + (uint32_t)(buf * TILEB);
        const uint32_t sR0 = tb + (uint32_t)((r0     ) * ROWB) + (uint32_t)(qc * 8);
        const uint32_t sR1 = tb + (uint32_t)((r0 +  8) * ROWB) + (uint32_t)(qc * 8);
        const uint32_t sR2 = tb + (uint32_t)((r0 + 16) * ROWB) + (uint32_t)(qc * 8);
        const uint32_t sR3 = tb + (uint32_t)((r0 + 24) * ROWB) + (uint32_t)(qc * 8);

        float acc[2][8][4];
        #pragma unroll
        for (int m = 0; m < 2; m++)
            #pragma unroll
            for (int nt = 0; nt < 8; nt++)
                #pragma unroll
                for (int r = 0; r < 4; r++) acc[m][nt][r] = 0.f;

        #pragma unroll
        for (int kt = 0; kt < 8; kt++) {
            const uint32_t cb = (uint32_t)(kt * 64);
            float2 f0 = lds64(sR0 + cb);
            float2 f1 = lds64(sR1 + cb);
            float2 f2 = lds64(sR0 + cb + 32);
            float2 f3 = lds64(sR1 + cb + 32);
            float2 g0 = lds64(sR2 + cb);
            float2 g1 = lds64(sR3 + cb);
            float2 g2 = lds64(sR2 + cb + 32);
            float2 g3 = lds64(sR3 + cb + 32);

            uint32_t a0[4], a1[4];
            a0[0] = cvt2h(f0.x, f0.y);
            a0[1] = cvt2h(f1.x, f1.y);
            a0[2] = cvt2h(f2.x, f2.y);
            a0[3] = cvt2h(f3.x, f3.y);
            a1[0] = cvt2h(g0.x, g0.y);
            a1[1] = cvt2h(g1.x, g1.y);
            a1[2] = cvt2h(g2.x, g2.y);
            a1[3] = cvt2h(g3.x, g3.y);

            #pragma unroll
            for (int nt = 0; nt < 8; nt++) {
                uint2 bb = __ldg(&g_wh[(nt * 8 + kt) * 32 + lane]);  // L1-hit
                mma_f16(acc[0][nt], a0, &bb.x);
                mma_f16(acc[1][nt], a1, &bb.x);
            }
        }

        // ---- epilogue: bias + ssp + W2 dot, quad shuffle-reduce ----
        float sum0 = 0.f, sum1 = 0.f, sum2 = 0.f, sum3 = 0.f;
        const int tg2 = qc * 2;
        #pragma unroll
        for (int nt = 0; nt < 8; nt++) {
            int c0 = nt * 8 + tg2;
            float2 b1v = __ldg(reinterpret_cast<const float2*>(b1 + c0));
            float2 w2v = __ldg(reinterpret_cast<const float2*>(W2 + c0));
            sum0 = fmaf(ssp(acc[0][nt][0] + b1v.x), w2v.x, sum0);
            sum0 = fmaf(ssp(acc[0][nt][1] + b1v.y), w2v.y, sum0);
            sum1 = fmaf(ssp(acc[0][nt][2] + b1v.x), w2v.x, sum1);
            sum1 = fmaf(ssp(acc[0][nt][3] + b1v.y), w2v.y, sum1);
            sum2 = fmaf(ssp(acc[1][nt][0] + b1v.x), w2v.x, sum2);
            sum2 = fmaf(ssp(acc[1][nt][1] + b1v.y), w2v.y, sum2);
            sum3 = fmaf(ssp(acc[1][nt][2] + b1v.x), w2v.x, sum3);
            sum3 = fmaf(ssp(acc[1][nt][3] + b1v.y), w2v.y, sum3);
        }
        sum0 += __shfl_xor_sync(0xffffffffu, sum0, 1);
        sum0 += __shfl_xor_sync(0xffffffffu, sum0, 2);
        sum1 += __shfl_xor_sync(0xffffffffu, sum1, 1);
        sum1 += __shfl_xor_sync(0xffffffffu, sum1, 2);
        sum2 += __shfl_xor_sync(0xffffffffu, sum2, 1);
        sum2 += __shfl_xor_sync(0xffffffffu, sum2, 2);
        sum3 += __shfl_xor_sync(0xffffffffu, sum3, 1);
        sum3 += __shfl_xor_sync(0xffffffffu, sum3, 2);

        float contrib = 0.f;
        if (qc == 0) {
            float scB2 = b2[0], scMean = mean[0], scStd = stddev[0];
            float sv[4] = {sum0, sum1, sum2, sum3};
            float tot = 0.f;
            #pragma unroll
            for (int m = 0; m < 4; m++) {
                int row = r0 + m * 8;
                int g = s * NATOM + row;
                float v = (sv[m] + scB2) * scStd + scMean;
                v += atomref[atomic_numbers[g]];
                v *= atom_mask[g];
                tot += v;
            }
            contrib = tot;
        }
        contrib += __shfl_xor_sync(0xffffffffu, contrib, 4);
        contrib += __shfl_xor_sync(0xffffffffu, contrib, 8);
        contrib += __shfl_xor_sync(0xffffffffu, contrib, 16);

        if (lane == 0) red[w] = contrib;
        __syncthreads();
        if (tid == 0) out[s] = red[0] + red[1] + red[2];
        __syncthreads();                 // buffer + red safe for next iteration

        buf ^= 1;
    }
}

// ---------------- host launch ----------------
extern "C" void kernel_launch(void* const* d_in, const int* in_sizes, int n_in,
                              void* d_out, int out_size) {
    const float* rep   = (const float*)d_in[0];
    const int*   zn    = (const int*)  d_in[1];
    const float* mask  = (const float*)d_in[2];
    const float* W1    = (const float*)d_in[3];
    const float* b1    = (const float*)d_in[4];
    const float* W2    = (const float*)d_in[5];
    const float* b2    = (const float*)d_in[6];
    const float* aref  = (const float*)d_in[7];
    const float* mean  = (const float*)d_in[8];
    const float* stdd  = (const float*)d_in[9];
    float* out = (float*)d_out;

    cudaFuncSetAttribute(atomwise_kernel, cudaFuncAttributeMaxDynamicSharedMemorySize, SMEMB);

    prep_w_kernel<<<32, 256>>>(W1);
    atomwise_kernel<<<GRIDC, 96, SMEMB>>>(rep, zn, mask, b1, W2, b2, aref, mean, stdd, out);
}

// round 14
// speedup vs baseline: 1.1741x; 1.1741x over previous
#include <cuda_runtime.h>
#include <cuda_fp16.h>
#include <cstdint>

// ---------------- problem constants ----------------
#define BATCH   2048
#define NATOM   96
#define NIN     128
#define NHID    64
#define SHIFTC  0.6931471805599453f
#define GRIDC   592            // 4 CTAs/SM x 148 SMs, single resident wave

// per-warp fp16 tile: 32 rows x (256B data + 16B pad) = 272B stride, bit-4 XOR swizzle
#define ROWB   272
#define WTILE  (32 * ROWB)     // 8704 B ; x2 bufs x3 warps = 52224 B/CTA
#define SMEMB  (6 * WTILE + 64)

// ---------------- precomputed W1 fp16 image (B-fragment layout) ----------------
// uint2 index = (nt*8 + kt)*32 + lane ; .x = b0 (k pair, khalf 0), .y = b1 (khalf 1)
__device__ __align__(16) uint2 g_wh[2048];   // 16 KB, L1/L2-resident

__global__ void prep_w_kernel(const float* __restrict__ W1) {
    int idx = blockIdx.x * blockDim.x + threadIdx.x;
    if (idx >= NIN * NHID) return;
    int k = idx >> 6;          // 0..127
    int n = idx & 63;          // 0..63
    __half h = __float2half_rn(W1[idx]);
    int nt = n >> 3, g = n & 7;
    int kt = k >> 4, kl = k & 15;
    int tg = (kl >> 1) & 3, br = kl >> 3, odd = kl & 1;
    uint32_t off = (uint32_t)((((nt * 8 + kt) * 32 + (g * 4 + tg)) * 8) + br * 4 + odd * 2);
    *reinterpret_cast<__half*>(reinterpret_cast<unsigned char*>(g_wh) + off) = h;
}

// ---------------- device helpers ----------------
__device__ __forceinline__ void mma_f16(float* c, const uint32_t* a, const uint32_t* b) {
    asm volatile(
        "mma.sync.aligned.m16n8k16.row.col.f32.f16.f16.f32 "
        "{%0,%1,%2,%3}, {%4,%5,%6,%7}, {%8,%9}, {%0,%1,%2,%3};"
        : "+f"(c[0]), "+f"(c[1]), "+f"(c[2]), "+f"(c[3])
        : "r"(a[0]), "r"(a[1]), "r"(a[2]), "r"(a[3]), "r"(b[0]), "r"(b[1]));
}

__device__ __forceinline__ void ldsm_x4(uint32_t* a, uint32_t saddr) {
    asm volatile("ldmatrix.sync.aligned.m8n8.x4.shared.b16 {%0,%1,%2,%3}, [%4];"
        : "=r"(a[0]), "=r"(a[1]), "=r"(a[2]), "=r"(a[3]) : "r"(saddr));
}

__device__ __forceinline__ float ssp(float z) {
    // shifted softplus, numerically stable
    return fmaxf(z, 0.f) + __logf(1.f + __expf(-fabsf(z))) - SHIFTC;
}

// cvt one fp32 row quad to fp16 and store to the swizzled warp tile
__device__ __forceinline__ void sts_row(uint32_t base, int r, int lane, float4 v) {
    __half2 h0 = __floats2half2_rn(v.x, v.y);
    __half2 h1 = __floats2half2_rn(v.z, v.w);
    uint32_t u0 = *reinterpret_cast<uint32_t*>(&h0);
    uint32_t u1 = *reinterpret_cast<uint32_t*>(&h1);
    uint32_t off = (uint32_t)(r * ROWB + ((lane * 8) ^ (((r >> 3) & 1) << 4)));
    asm volatile("st.shared.v2.u32 [%0], {%1,%2};" :: "r"(base + off), "r"(u0), "r"(u1));
}

// ---------------- main fused kernel ----------------
// Synthesis of R11 (best: warp-private fp16 tile + ldmatrix, 25.3us) and R13's
// cross-sample prefetch, done PER-WARP with register staging: while sample s runs
// its 8-kt MMA loop, sample s+1's 32 rows stream in as 4 batches of 8 coalesced
// LDG.128 interleaved at kt=0..4 (each batch gets ~2 kt of MMA work as latency
// cover).  No CTA-wide fill convoy; one __syncthreads per sample (red reuse,
// parity-buffered), issued after next sample's loads are already in flight.
__global__ void __launch_bounds__(96, 4)
atomwise_kernel(const float* __restrict__ rep,
                const int*   __restrict__ atomic_numbers,
                const float* __restrict__ atom_mask,
                const float* __restrict__ b1,
                const float* __restrict__ W2,
                const float* __restrict__ b2,
                const float* __restrict__ atomref,
                const float* __restrict__ mean,
                const float* __restrict__ stddev,
                float*       __restrict__ out) {
    extern __shared__ __align__(16) unsigned char smem[];
    float* red = reinterpret_cast<float*>(smem + 6 * WTILE);   // red[2][4]

    const int tid  = threadIdx.x;
    const int w    = tid >> 5;          // warp 0..2
    const int lane = tid & 31;

    const int qr = lane >> 2;           // 0..7 (row group)
    const int qc = lane & 3;            // 0..3 (col pair)
    const int r0 = w * 32 + qr;         // rows r0, r0+8, r0+16, r0+24 (warp-local +w*32)

    const uint32_t sb0 = (uint32_t)__cvta_generic_to_shared(smem) + (uint32_t)(w * 2 * WTILE);
    const uint32_t sb1 = sb0 + WTILE;

    // ldmatrix lane addressing
    const uint32_t rsel = lane & 15;
    const uint32_t csel = (uint32_t)(lane >> 4) * 16;

    // ---- prologue: full fill of buf0 for first sample ----
    {
        const float4* rowsrc = reinterpret_cast<const float4*>(
            rep + (size_t)blockIdx.x * (NATOM * NIN) + (w * 32) * NIN);
        #pragma unroll
        for (int rr = 0; rr < 32; rr += 8) {
            float4 v[8];
            #pragma unroll
            for (int j = 0; j < 8; j++) v[j] = __ldg(rowsrc + (rr + j) * 32 + lane);
            #pragma unroll
            for (int j = 0; j < 8; j++) sts_row(sb0, rr + j, lane, v[j]);
        }
    }
    __syncwarp();

    int buf = 0;
    int par = 0;
    for (int s = blockIdx.x; s < BATCH; s += GRIDC) {
        const int snext = s + GRIDC;
        const bool pf = (snext < BATCH);
        const uint32_t tb = buf ? sb1 : sb0;
        const uint32_t nb = buf ? sb0 : sb1;
        const float4* nsrc = reinterpret_cast<const float4*>(
            rep + (size_t)snext * (NATOM * NIN) + (w * 32) * NIN);

        float acc[2][8][4];
        #pragma unroll
        for (int m = 0; m < 2; m++)
            #pragma unroll
            for (int nt = 0; nt < 8; nt++)
                #pragma unroll
                for (int r = 0; r < 4; r++) acc[m][nt][r] = 0.f;

        float4 v[8];
        if (pf) {
            #pragma unroll
            for (int j = 0; j < 8; j++) v[j] = __ldg(nsrc + j * 32 + lane);
        }

        #pragma unroll
        for (int kt = 0; kt < 8; kt++) {
            uint32_t a0[4], a1[4];
            {
                uint32_t r = rsel;
                uint32_t col = ((uint32_t)(kt * 32) + csel) ^ (((r >> 3) & 1) << 4);
                ldsm_x4(a0, tb + r * ROWB + col);
            }
            {
                uint32_t r = 16 + rsel;
                uint32_t col = ((uint32_t)(kt * 32) + csel) ^ (((r >> 3) & 1) << 4);
                ldsm_x4(a1, tb + r * ROWB + col);
            }

            #pragma unroll
            for (int nt = 0; nt < 8; nt++) {
                uint2 bb = __ldg(&g_wh[(nt * 8 + kt) * 32 + lane]);  // L1-hit
                mma_f16(acc[0][nt], a0, &bb.x);
                mma_f16(acc[1][nt], a1, &bb.x);
            }

            // cross-sample prefetch stage: store batch kt, then issue batch kt+1
            if (pf && kt < 4) {
                #pragma unroll
                for (int j = 0; j < 8; j++) sts_row(nb, kt * 8 + j, lane, v[j]);
                if (kt < 3) {
                    #pragma unroll
                    for (int j = 0; j < 8; j++)
                        v[j] = __ldg(nsrc + ((kt + 1) * 8 + j) * 32 + lane);
                }
            }
        }

        // ---- epilogue: bias + ssp + W2 dot, quad shuffle-reduce ----
        float sum0 = 0.f, sum1 = 0.f, sum2 = 0.f, sum3 = 0.f;
        const int tg2 = qc * 2;
        #pragma unroll
        for (int nt = 0; nt < 8; nt++) {
            int c0 = nt * 8 + tg2;
            float2 b1v = __ldg(reinterpret_cast<const float2*>(b1 + c0));
            float2 w2v = __ldg(reinterpret_cast<const float2*>(W2 + c0));
            sum0 = fmaf(ssp(acc[0][nt][0] + b1v.x), w2v.x, sum0);
            sum0 = fmaf(ssp(acc[0][nt][1] + b1v.y), w2v.y, sum0);
            sum1 = fmaf(ssp(acc[0][nt][2] + b1v.x), w2v.x, sum1);
            sum1 = fmaf(ssp(acc[0][nt][3] + b1v.y), w2v.y, sum1);
            sum2 = fmaf(ssp(acc[1][nt][0] + b1v.x), w2v.x, sum2);
            sum2 = fmaf(ssp(acc[1][nt][1] + b1v.y), w2v.y, sum2);
            sum3 = fmaf(ssp(acc[1][nt][2] + b1v.x), w2v.x, sum3);
            sum3 = fmaf(ssp(acc[1][nt][3] + b1v.y), w2v.y, sum3);
        }
        sum0 += __shfl_xor_sync(0xffffffffu, sum0, 1);
        sum0 += __shfl_xor_sync(0xffffffffu, sum0, 2);
        sum1 += __shfl_xor_sync(0xffffffffu, sum1, 1);
        sum1 += __shfl_xor_sync(0xffffffffu, sum1, 2);
        sum2 += __shfl_xor_sync(0xffffffffu, sum2, 1);
        sum2 += __shfl_xor_sync(0xffffffffu, sum2, 2);
        sum3 += __shfl_xor_sync(0xffffffffu, sum3, 1);
        sum3 += __shfl_xor_sync(0xffffffffu, sum3, 2);

        float contrib = 0.f;
        if (qc == 0) {
            float scB2 = b2[0], scMean = mean[0], scStd = stddev[0];
            float sv[4] = {sum0, sum1, sum2, sum3};
            float tot = 0.f;
            #pragma unroll
            for (int m = 0; m < 4; m++) {
                int row = r0 + m * 8;
                int g = s * NATOM + row;
                float vv = (sv[m] + scB2) * scStd + scMean;
                vv += atomref[atomic_numbers[g]];
                vv *= atom_mask[g];
                tot += vv;
            }
            contrib = tot;
        }
        contrib += __shfl_xor_sync(0xffffffffu, contrib, 4);
        contrib += __shfl_xor_sync(0xffffffffu, contrib, 8);
        contrib += __shfl_xor_sync(0xffffffffu, contrib, 16);

        if (lane == 0) red[par * 4 + w] = contrib;
        __syncthreads();     // red ready + prev tile's STS visible warp-wide
        if (tid == 0) out[s] = red[par * 4 + 0] + red[par * 4 + 1] + red[par * 4 + 2];

        buf ^= 1;
        par ^= 1;
    }
}

// ---------------- host launch ----------------
extern "C" void kernel_launch(void* const* d_in, const int* in_sizes, int n_in,
                              void* d_out, int out_size) {
    const float* rep   = (const float*)d_in[0];
    const int*   zn    = (const int*)  d_in[1];
    const float* mask  = (const float*)d_in[2];
    const float* W1    = (const float*)d_in[3];
    const float* b1    = (const float*)d_in[4];
    const float* W2    = (const float*)d_in[5];
    const float* b2    = (const float*)d_in[6];
    const float* aref  = (const float*)d_in[7];
    const float* mean  = (const float*)d_in[8];
    const float* stdd  = (const float*)d_in[9];
    float* out = (float*)d_out;

    cudaFuncSetAttribute(atomwise_kernel, cudaFuncAttributeMaxDynamicSharedMemorySize, SMEMB);

    prep_w_kernel<<<32, 256>>>(W1);
    atomwise_kernel<<<GRIDC, 96, SMEMB>>>(rep, zn, mask, b1, W2, b2, aref, mean, stdd, out);
}

// round 15
// speedup vs baseline: 1.2724x; 1.0837x over previous
#include <cuda_runtime.h>
#include <cuda_fp16.h>
#include <cstdint>

// ---------------- problem constants ----------------
#define BATCH   2048
#define NATOM   96
#define NIN     128
#define NHID    64
#define LOG2E   1.4426950408889634f
#define LN2     0.6931471805599453f

// per-warp fp16 tile: 32 rows x (256B data + 16B pad) = 272B stride, bit-4 XOR swizzle
#define ROWB   272
#define WTILE  (32 * ROWB)     // 8704 B per warp

// ---------------- precomputed W1 fp16 image (B-fragment layout) ----------------
// uint2 index = (nt*8 + kt)*32 + lane ; .x = b0 (k pair, khalf 0), .y = b1 (khalf 1)
__device__ __align__(16) uint2 g_wh[2048];   // 16 KB, L1/L2-resident

__global__ void prep_w_kernel(const float* __restrict__ W1) {
    int idx = blockIdx.x * blockDim.x + threadIdx.x;
    if (idx >= NIN * NHID) return;
    int k = idx >> 6;          // 0..127
    int n = idx & 63;          // 0..63
    __half h = __float2half_rn(W1[idx]);
    int nt = n >> 3, g = n & 7;
    int kt = k >> 4, kl = k & 15;
    int tg = (kl >> 1) & 3, br = kl >> 3, odd = kl & 1;
    uint32_t off = (uint32_t)((((nt * 8 + kt) * 32 + (g * 4 + tg)) * 8) + br * 4 + odd * 2);
    *reinterpret_cast<__half*>(reinterpret_cast<unsigned char*>(g_wh) + off) = h;
}

// ---------------- device helpers ----------------
__device__ __forceinline__ void mma_f16(float* c, const uint32_t* a, const uint32_t* b) {
    asm volatile(
        "mma.sync.aligned.m16n8k16.row.col.f32.f16.f16.f32 "
        "{%0,%1,%2,%3}, {%4,%5,%6,%7}, {%8,%9}, {%0,%1,%2,%3};"
        : "+f"(c[0]), "+f"(c[1]), "+f"(c[2]), "+f"(c[3])
        : "r"(a[0]), "r"(a[1]), "r"(a[2]), "r"(a[3]), "r"(b[0]), "r"(b[1]));
}

__device__ __forceinline__ void ldsm_x4(uint32_t* a, uint32_t saddr) {
    asm volatile("ldmatrix.sync.aligned.m8n8.x4.shared.b16 {%0,%1,%2,%3}, [%4];"
        : "=r"(a[0]), "=r"(a[1]), "=r"(a[2]), "=r"(a[3]) : "r"(saddr));
}

__device__ __forceinline__ float ex2f(float x) {
    float r; asm("ex2.approx.f32 %0, %1;" : "=f"(r) : "f"(x)); return r;
}
__device__ __forceinline__ float lg2f(float x) {
    float r; asm("lg2.approx.f32 %0, %1;" : "=f"(r) : "f"(x)); return r;
}

// column-block fill: block c holds k = 32c..32c+31 of all 32 rows.
// lane -> (row0 = lane>>3, chunk = lane&7); j covers rows row0, row0+4, ..., row0+28.
__device__ __forceinline__ void load_blk(const float4* b4, int c, int lane, float4* v) {
    int row0 = lane >> 3, chunk = lane & 7;
    #pragma unroll
    for (int j = 0; j < 8; j++)
        v[j] = __ldg(b4 + (j * 4 + row0) * 32 + c * 8 + chunk);
}
__device__ __forceinline__ void sts_blk(uint32_t sb, int c, int lane, const float4* v) {
    int row0 = lane >> 3, chunk = lane & 7;
    #pragma unroll
    for (int j = 0; j < 8; j++) {
        int r = j * 4 + row0;
        __half2 h0 = __floats2half2_rn(v[j].x, v[j].y);
        __half2 h1 = __floats2half2_rn(v[j].z, v[j].w);
        uint32_t u0 = *reinterpret_cast<uint32_t*>(&h0);
        uint32_t u1 = *reinterpret_cast<uint32_t*>(&h1);
        uint32_t off = (uint32_t)(r * ROWB + ((c * 64 + chunk * 8) ^ (((r >> 3) & 1) << 4)));
        asm volatile("st.shared.v2.u32 [%0], {%1,%2};" :: "r"(sb + off), "r"(u0), "r"(u1));
    }
}

// one kt step: 2 ldmatrix + 8 B-loads + 16 MMAs
__device__ __forceinline__ void mma_kt(int kt, uint32_t tb, uint32_t rsel, uint32_t csel,
                                       int lane, float acc[2][8][4]) {
    uint32_t a0[4], a1[4];
    {
        uint32_t r = rsel;
        uint32_t col = ((uint32_t)(kt * 32) + csel) ^ (((r >> 3) & 1) << 4);
        ldsm_x4(a0, tb + r * ROWB + col);
    }
    {
        uint32_t r = 16 + rsel;
        uint32_t col = ((uint32_t)(kt * 32) + csel) ^ (((r >> 3) & 1) << 4);
        ldsm_x4(a1, tb + r * ROWB + col);
    }
    #pragma unroll
    for (int nt = 0; nt < 8; nt++) {
        uint2 bb = __ldg(&g_wh[(nt * 8 + kt) * 32 + lane]);  // L1-hit after warmup
        mma_f16(acc[0][nt], a0, &bb.x);
        mma_f16(acc[1][nt], a1, &bb.x);
    }
}

// ---------------- main fused kernel: one CTA (3 warps) per batch sample ----------------
// R11 architecture (best measured) + two targeted fixes:
// (a) k-blocked fill interleaved with MMA: store block c, issue block c+1 loads,
//     run kt=2c,2c+1 under them — only block 0's latency stays exposed (~650cyc vs
//     R11's ~2600 serial fill).
// (b) lean ssp: ssp(z) = ln2*lg2(0.5+0.5*ex2(z*log2e)) — exact at our |z|, ln2
//     folded into the stddev multiply, b1*log2e hoisted: 3 FMA + 2 MUFU per ssp.
__global__ void __launch_bounds__(96, 5)
atomwise_kernel(const float* __restrict__ rep,
                const int*   __restrict__ atomic_numbers,
                const float* __restrict__ atom_mask,
                const float* __restrict__ b1,
                const float* __restrict__ W2,
                const float* __restrict__ b2,
                const float* __restrict__ atomref,
                const float* __restrict__ mean,
                const float* __restrict__ stddev,
                float*       __restrict__ out) {
    __shared__ __align__(16) unsigned char smA[3][WTILE];
    __shared__ float red[4];

    const int tid  = threadIdx.x;
    const int w    = tid >> 5;          // warp 0..2
    const int lane = tid & 31;
    const int b    = blockIdx.x;

    const int qr = lane >> 2;           // 0..7 (row group)
    const int qc = lane & 3;            // 0..3 (col pair)
    const int r0 = w * 32 + qr;

    const float* xb = rep + (size_t)b * (NATOM * NIN);
    const float4* rowsrc = reinterpret_cast<const float4*>(xb + (w * 32) * NIN);
    const uint32_t sbase = (uint32_t)__cvta_generic_to_shared(&smA[w][0]);

    const uint32_t rsel = lane & 15;
    const uint32_t csel = (uint32_t)(lane >> 4) * 16;

    float acc[2][8][4];
    #pragma unroll
    for (int m = 0; m < 2; m++)
        #pragma unroll
        for (int nt = 0; nt < 8; nt++)
            #pragma unroll
            for (int r = 0; r < 4; r++) acc[m][nt][r] = 0.f;

    // ---- software-pipelined fill/MMA ----
    float4 v[8];
    load_blk(rowsrc, 0, lane, v);       // block 0 in flight
    sts_blk(sbase, 0, lane, v);         // waits on block 0
    __syncwarp();
    load_blk(rowsrc, 1, lane, v);       // block 1 in flight
    mma_kt(0, sbase, rsel, csel, lane, acc);
    mma_kt(1, sbase, rsel, csel, lane, acc);
    sts_blk(sbase, 1, lane, v);
    __syncwarp();
    load_blk(rowsrc, 2, lane, v);
    mma_kt(2, sbase, rsel, csel, lane, acc);
    mma_kt(3, sbase, rsel, csel, lane, acc);
    sts_blk(sbase, 2, lane, v);
    __syncwarp();
    load_blk(rowsrc, 3, lane, v);
    mma_kt(4, sbase, rsel, csel, lane, acc);
    mma_kt(5, sbase, rsel, csel, lane, acc);
    sts_blk(sbase, 3, lane, v);
    __syncwarp();
    mma_kt(6, sbase, rsel, csel, lane, acc);
    mma_kt(7, sbase, rsel, csel, lane, acc);

    // ---- epilogue: lean ssp + W2 dot, quad shuffle-reduce ----
    // raw sums accumulate lg2-space values; ln2 is folded into the stddev scale.
    float sum0 = 0.f, sum1 = 0.f, sum2 = 0.f, sum3 = 0.f;
    const int tg2 = qc * 2;
    #pragma unroll
    for (int nt = 0; nt < 8; nt++) {
        int c0 = nt * 8 + tg2;
        float2 b1v = __ldg(reinterpret_cast<const float2*>(b1 + c0));
        float2 w2v = __ldg(reinterpret_cast<const float2*>(W2 + c0));
        float b1x = b1v.x * LOG2E, b1y = b1v.y * LOG2E;

        sum0 = fmaf(lg2f(fmaf(ex2f(fmaf(acc[0][nt][0], LOG2E, b1x)), 0.5f, 0.5f)), w2v.x, sum0);
        sum0 = fmaf(lg2f(fmaf(ex2f(fmaf(acc[0][nt][1], LOG2E, b1y)), 0.5f, 0.5f)), w2v.y, sum0);
        sum1 = fmaf(lg2f(fmaf(ex2f(fmaf(acc[0][nt][2], LOG2E, b1x)), 0.5f, 0.5f)), w2v.x, sum1);
        sum1 = fmaf(lg2f(fmaf(ex2f(fmaf(acc[0][nt][3], LOG2E, b1y)), 0.5f, 0.5f)), w2v.y, sum1);
        sum2 = fmaf(lg2f(fmaf(ex2f(fmaf(acc[1][nt][0], LOG2E, b1x)), 0.5f, 0.5f)), w2v.x, sum2);
        sum2 = fmaf(lg2f(fmaf(ex2f(fmaf(acc[1][nt][1], LOG2E, b1y)), 0.5f, 0.5f)), w2v.y, sum2);
        sum3 = fmaf(lg2f(fmaf(ex2f(fmaf(acc[1][nt][2], LOG2E, b1x)), 0.5f, 0.5f)), w2v.x, sum3);
        sum3 = fmaf(lg2f(fmaf(ex2f(fmaf(acc[1][nt][3], LOG2E, b1y)), 0.5f, 0.5f)), w2v.y, sum3);
    }
    sum0 += __shfl_xor_sync(0xffffffffu, sum0, 1);
    sum0 += __shfl_xor_sync(0xffffffffu, sum0, 2);
    sum1 += __shfl_xor_sync(0xffffffffu, sum1, 1);
    sum1 += __shfl_xor_sync(0xffffffffu, sum1, 2);
    sum2 += __shfl_xor_sync(0xffffffffu, sum2, 1);
    sum2 += __shfl_xor_sync(0xffffffffu, sum2, 2);
    sum3 += __shfl_xor_sync(0xffffffffu, sum3, 1);
    sum3 += __shfl_xor_sync(0xffffffffu, sum3, 2);

    float contrib = 0.f;
    if (qc == 0) {
        float scStd = stddev[0];
        float scStdL = scStd * LN2;                    // folds the lg2->ln conversion
        float cbase = fmaf(b2[0], scStd, mean[0]);
        float sv[4] = {sum0, sum1, sum2, sum3};
        float tot = 0.f;
        #pragma unroll
        for (int m = 0; m < 4; m++) {
            int row = r0 + m * 8;
            int g = b * NATOM + row;
            float vv = fmaf(sv[m], scStdL, cbase + atomref[atomic_numbers[g]]);
            tot += vv * atom_mask[g];
        }
        contrib = tot;
    }
    contrib += __shfl_xor_sync(0xffffffffu, contrib, 4);
    contrib += __shfl_xor_sync(0xffffffffu, contrib, 8);
    contrib += __shfl_xor_sync(0xffffffffu, contrib, 16);

    if (lane == 0) red[w] = contrib;
    __syncthreads();
    if (tid == 0) out[b] = red[0] + red[1] + red[2];
}

// ---------------- host launch ----------------
extern "C" void kernel_launch(void* const* d_in, const int* in_sizes, int n_in,
                              void* d_out, int out_size) {
    const float* rep   = (const float*)d_in[0];
    const int*   zn    = (const int*)  d_in[1];
    const float* mask  = (const float*)d_in[2];
    const float* W1    = (const float*)d_in[3];
    const float* b1    = (const float*)d_in[4];
    const float* W2    = (const float*)d_in[5];
    const float* b2    = (const float*)d_in[6];
    const float* aref  = (const float*)d_in[7];
    const float* mean  = (const float*)d_in[8];
    const float* stdd  = (const float*)d_in[9];
    float* out = (float*)d_out;

    prep_w_kernel<<<32, 256>>>(W1);
    atomwise_kernel<<<BATCH, 96>>>(rep, zn, mask, b1, W2, b2, aref, mean, stdd, out);
}